// round 15
// baseline (speedup 1.0000x reference)
#include <cuda_runtime.h>
#include <math.h>
#include <stdint.h>

#define B_    8
#define L_    8192
#define DM    128
#define DI    256
#define DS    16
#define DTR   8
#define NROWS (B_*L_)
#define TC    64
#define NCH   (L_/TC)

// ---------------- scratch ----------------
__device__ float g_xn [(size_t)NROWS*DM];
__device__ float g_xz [(size_t)NROWS*512];
__device__ float g_u2 [(size_t)NROWS*DI];
__device__ float g_dbc[(size_t)NROWS*40];
__device__ float g_y  [(size_t)NROWS*DI];
__device__ float g_dec[B_*NCH*DI*DS];
__device__ float g_snd[B_*NCH*DI*DS];
__device__ float g_hin[B_*NCH*DI*DS];
#define WPI 0
#define WPX 262144
#define WPO 303104
#define WPT 434176
__device__ float g_wp[WPT];

// ---------------- helpers ----------------
__device__ __forceinline__ float tf32r(float x) {
    uint32_t r;
    asm("cvt.rna.tf32.f32 %0, %1;" : "=r"(r) : "f"(x));
    return __uint_as_float(r);
}
__device__ __forceinline__ uint32_t s2u(const void* p) {
    uint32_t r;
    asm("{ .reg .u64 t; cvta.to.shared.u64 t, %1; cvt.u32.u64 %0, t; }" : "=r"(r) : "l"(p));
    return r;
}
#define MMA_TF32(acc, A0, A1, A2, A3, B0, B1)                                  \
    asm volatile(                                                              \
        "mma.sync.aligned.m16n8k8.row.col.f32.tf32.tf32.f32 "                  \
        "{%0,%1,%2,%3}, {%4,%5,%6,%7}, {%8,%9}, {%0,%1,%2,%3};"                \
        : "+f"((acc)[0]), "+f"((acc)[1]), "+f"((acc)[2]), "+f"((acc)[3])       \
        : "r"(A0), "r"(A1), "r"(A2), "r"(A3), "r"(B0), "r"(B1))

// ---------------- weight prep ----------------
__global__ void prep_w(const float* __restrict__ in_w, const float* __restrict__ xproj_w,
                       const float* __restrict__ out_w, float* __restrict__ wp) {
    int i = blockIdx.x * blockDim.x + threadIdx.x;
    if (i < WPX)            wp[i] = tf32r(in_w[i]);
    else if (i < WPO)       wp[i] = tf32r(xproj_w[i - WPX]);
    else if (i < WPT)       wp[i] = tf32r(out_w[i - WPO]);
}

// ---------------- init ----------------
__global__ void init_h_kernel(const float* __restrict__ x, const float* __restrict__ pw,
                              const float* __restrict__ pb, float* __restrict__ h) {
    int idx = blockIdx.x * blockDim.x + threadIdx.x;
    if (idx >= NROWS * DM) return;
    int d = idx & (DM - 1);
    int row = idx >> 7;
    int b = row >> 13;
    int l = row & (L_ - 1);
    float acc = pb[d];
#pragma unroll
    for (int c = 0; c < 3; c++)
        acc += x[(b * 3 + c) * L_ + l] * pw[d * 3 + c];
    h[idx] = acc;
}

// ---------------- layernorm (layer-0 only) ----------------
__global__ void ln_kernel(const float* __restrict__ in, const float* __restrict__ w,
                          const float* __restrict__ bias, float* __restrict__ out,
                          int nrows) {
    int gwarp = (blockIdx.x * blockDim.x + threadIdx.x) >> 5;
    int lane  = threadIdx.x & 31;
    if (gwarp >= nrows) return;
    const float4 v = *reinterpret_cast<const float4*>(&in[(size_t)gwarp * DM + lane * 4]);
    float s = v.x + v.y + v.z + v.w;
#pragma unroll
    for (int o = 16; o; o >>= 1) s += __shfl_xor_sync(0xffffffffu, s, o);
    float mu = s * (1.0f / DM);
    float d0 = v.x - mu, d1 = v.y - mu, d2 = v.z - mu, d3 = v.w - mu;
    float q = d0 * d0 + d1 * d1 + d2 * d2 + d3 * d3;
#pragma unroll
    for (int o = 16; o; o >>= 1) q += __shfl_xor_sync(0xffffffffu, q, o);
    float r = rsqrtf(q * (1.0f / DM) + 1e-5f);
    const float4 wv = *reinterpret_cast<const float4*>(&w[lane * 4]);
    const float4 bv = *reinterpret_cast<const float4*>(&bias[lane * 4]);
    float4 o4;
    o4.x = tf32r(d0 * r * wv.x + bv.x);
    o4.y = tf32r(d1 * r * wv.y + bv.y);
    o4.z = tf32r(d2 * r * wv.z + bv.z);
    o4.w = tf32r(d3 * r * wv.w + bv.w);
    *reinterpret_cast<float4*>(&out[(size_t)gwarp * DM + lane * 4]) = o4;
}

// ---------------- common GEMM constants ----------------
#define TBK 32
#define PITCH 36

// ---------------- in_proj GEMM: 128x128 tile, TBK=32 ----------------
#define ISTG (128*PITCH)
#define IGSMB (2*2*ISTG*4)

__global__ __launch_bounds__(256) void gemm_in(
    const float* __restrict__ A, const float* __restrict__ W,
    float* __restrict__ C) {
    extern __shared__ float sm[];
    float* As = sm;
    float* Ws = sm + 2 * ISTG;
    const int K = DM;
    int tid  = threadIdx.x;
    int warp = tid >> 5;
    int lane = tid & 31;
    int gid  = lane >> 2;
    int tig  = lane & 3;
    int wm = (warp >> 2) * 64;
    int wn = (warp & 3) * 32;
    int m0 = blockIdx.y * 128;
    int n0 = blockIdx.x * 128;

    float acc[4][4][4];
#pragma unroll
    for (int i = 0; i < 4; i++)
#pragma unroll
        for (int j = 0; j < 4; j++)
#pragma unroll
            for (int r = 0; r < 4; r++) acc[i][j][r] = 0.0f;

    auto prefetch = [&](float* as, float* ws, int k0) {
#pragma unroll
        for (int r = 0; r < 4; r++) {
            int lin = tid + r * 256;
            int row = lin >> 3;
            int c   = (lin & 7) * 4;
            uint32_t d = s2u(&as[row * PITCH + c]);
            const float* s = &A[(size_t)(m0 + row) * K + k0 + c];
            asm volatile("cp.async.cg.shared.global [%0], [%1], 16;" :: "r"(d), "l"(s) : "memory");
        }
#pragma unroll
        for (int r = 0; r < 4; r++) {
            int lin = tid + r * 256;
            int row = lin >> 3;
            int c   = (lin & 7) * 4;
            uint32_t d = s2u(&ws[row * PITCH + c]);
            const float* s = &W[(size_t)(n0 + row) * K + k0 + c];
            asm volatile("cp.async.cg.shared.global [%0], [%1], 16;" :: "r"(d), "l"(s) : "memory");
        }
    };

    prefetch(As, Ws, 0);
    asm volatile("cp.async.commit_group;" ::: "memory");
    const int nt = K / TBK;
    for (int it = 0; it < nt; it++) {
        if (it + 1 < nt)
            prefetch(As + ((it + 1) & 1) * ISTG, Ws + ((it + 1) & 1) * ISTG,
                     (it + 1) * TBK);
        asm volatile("cp.async.commit_group;" ::: "memory");
        asm volatile("cp.async.wait_group 1;" ::: "memory");
        __syncthreads();
        const uint32_t* a_s = reinterpret_cast<const uint32_t*>(As + (it & 1) * ISTG);
        const uint32_t* w_s = reinterpret_cast<const uint32_t*>(Ws + (it & 1) * ISTG);
#pragma unroll
        for (int kk = 0; kk < 4; kk++) {
            uint32_t a[4][4], b[4][2];
#pragma unroll
            for (int mf = 0; mf < 4; mf++) {
                int rb = wm + mf * 16;
                a[mf][0] = a_s[(rb + gid)     * PITCH + kk * 8 + tig];
                a[mf][1] = a_s[(rb + gid + 8) * PITCH + kk * 8 + tig];
                a[mf][2] = a_s[(rb + gid)     * PITCH + kk * 8 + tig + 4];
                a[mf][3] = a_s[(rb + gid + 8) * PITCH + kk * 8 + tig + 4];
            }
#pragma unroll
            for (int nf = 0; nf < 4; nf++) {
                int nb = wn + nf * 8 + gid;
                b[nf][0] = w_s[nb * PITCH + kk * 8 + tig];
                b[nf][1] = w_s[nb * PITCH + kk * 8 + tig + 4];
            }
#pragma unroll
            for (int mf = 0; mf < 4; mf++)
#pragma unroll
                for (int nf = 0; nf < 4; nf++)
                    MMA_TF32(acc[mf][nf], a[mf][0], a[mf][1], a[mf][2], a[mf][3],
                             b[nf][0], b[nf][1]);
        }
        __syncthreads();
    }

#pragma unroll
    for (int mf = 0; mf < 4; mf++) {
        int row0 = m0 + wm + mf * 16 + gid;
#pragma unroll
        for (int nf = 0; nf < 4; nf++) {
            int col = n0 + wn + nf * 8 + tig * 2;
            size_t o0 = (size_t)row0 * 512 + col;
            size_t o1 = (size_t)(row0 + 8) * 512 + col;
            C[o0]     = acc[mf][nf][0];
            C[o0 + 1] = acc[mf][nf][1];
            C[o1]     = acc[mf][nf][2];
            C[o1 + 1] = acc[mf][nf][3];
        }
    }
}

// ---------------- x_proj GEMM: 128x64 tile (N=40) ----------------
#define XA_STG (128*PITCH)
#define XW_STG (64*PITCH)
#define XGSMB (2*(XA_STG+XW_STG)*4)

__global__ __launch_bounds__(256) void gemm_xp(
    const float* __restrict__ A, const float* __restrict__ W,
    float* __restrict__ C, int N, int K) {
    extern __shared__ float sm[];
    float* As = sm;
    float* Ws = sm + 2 * XA_STG;
    int tid  = threadIdx.x;
    int warp = tid >> 5;
    int lane = tid & 31;
    int gid  = lane >> 2;
    int tig  = lane & 3;
    int wm = (warp >> 1) * 32;
    int wn = (warp & 1) * 32;
    int m0 = blockIdx.y * 128;
    int nt = K / TBK;

    float acc[2][4][4];
#pragma unroll
    for (int i = 0; i < 2; i++)
#pragma unroll
        for (int j = 0; j < 4; j++)
#pragma unroll
            for (int r = 0; r < 4; r++) acc[i][j][r] = 0.0f;

    auto prefetch = [&](float* as, float* ws, int k0) {
#pragma unroll
        for (int r = 0; r < 4; r++) {
            int lin = tid + r * 256;
            int row = lin >> 3;
            int c   = (lin & 7) * 4;
            uint32_t d = s2u(&as[row * PITCH + c]);
            const float* s = &A[(size_t)(m0 + row) * K + k0 + c];
            asm volatile("cp.async.cg.shared.global [%0], [%1], 16;" :: "r"(d), "l"(s) : "memory");
        }
#pragma unroll
        for (int r = 0; r < 2; r++) {
            int lin = tid + r * 256;
            int row = lin >> 3;
            int c   = (lin & 7) * 4;
            if (row < N) {
                uint32_t d = s2u(&ws[row * PITCH + c]);
                const float* s = &W[(size_t)row * K + k0 + c];
                asm volatile("cp.async.cg.shared.global [%0], [%1], 16;" :: "r"(d), "l"(s) : "memory");
            }
        }
    };

    prefetch(As, Ws, 0);
    asm volatile("cp.async.commit_group;" ::: "memory");
    for (int it = 0; it < nt; it++) {
        if (it + 1 < nt)
            prefetch(As + ((it + 1) & 1) * XA_STG, Ws + ((it + 1) & 1) * XW_STG,
                     (it + 1) * TBK);
        asm volatile("cp.async.commit_group;" ::: "memory");
        asm volatile("cp.async.wait_group 1;" ::: "memory");
        __syncthreads();
        const uint32_t* a_s = reinterpret_cast<const uint32_t*>(As + (it & 1) * XA_STG);
        const uint32_t* w_s = reinterpret_cast<const uint32_t*>(Ws + (it & 1) * XW_STG);
#pragma unroll
        for (int kk = 0; kk < 4; kk++) {
            uint32_t a[2][4], b[4][2];
#pragma unroll
            for (int mf = 0; mf < 2; mf++) {
                int rb = wm + mf * 16;
                a[mf][0] = a_s[(rb + gid)     * PITCH + kk * 8 + tig];
                a[mf][1] = a_s[(rb + gid + 8) * PITCH + kk * 8 + tig];
                a[mf][2] = a_s[(rb + gid)     * PITCH + kk * 8 + tig + 4];
                a[mf][3] = a_s[(rb + gid + 8) * PITCH + kk * 8 + tig + 4];
            }
#pragma unroll
            for (int nf = 0; nf < 4; nf++) {
                int nb = wn + nf * 8 + gid;
                b[nf][0] = w_s[nb * PITCH + kk * 8 + tig];
                b[nf][1] = w_s[nb * PITCH + kk * 8 + tig + 4];
            }
#pragma unroll
            for (int mf = 0; mf < 2; mf++)
#pragma unroll
                for (int nf = 0; nf < 4; nf++)
                    MMA_TF32(acc[mf][nf], a[mf][0], a[mf][1], a[mf][2], a[mf][3],
                             b[nf][0], b[nf][1]);
        }
        __syncthreads();
    }

#pragma unroll
    for (int mf = 0; mf < 2; mf++) {
        int row0 = m0 + wm + mf * 16 + gid;
#pragma unroll
        for (int nf = 0; nf < 4; nf++) {
            int col = wn + nf * 8 + tig * 2;
            if (col < N) {
                size_t o0 = (size_t)row0 * N + col;
                size_t o1 = (size_t)(row0 + 8) * N + col;
                C[o0] = acc[mf][nf][0];
                if (col + 1 < N) C[o0 + 1] = acc[mf][nf][1];
                C[o1] = acc[mf][nf][2];
                if (col + 1 < N) C[o1 + 1] = acc[mf][nf][3];
            }
        }
    }
}

// ---------------- out-proj GEMM: 64x128 tile + residual + fused LayerNorm ----------
#define OA_STG (64*PITCH)
#define OW_STG (128*PITCH)
#define OGSMB (2*(OA_STG+OW_STG)*4)

template <bool LAST>
__global__ __launch_bounds__(256) void gemm_out_fused(
    const float* __restrict__ A, const float* __restrict__ W,
    float* __restrict__ h, float* __restrict__ xn,
    const float* __restrict__ lnw, const float* __restrict__ lnb) {
    extern __shared__ float sm[];
    float* As = sm;
    float* Ws = sm + 2 * OA_STG;
    __shared__ float red[2][64][4];
    const int K = DI;
    int tid  = threadIdx.x;
    int warp = tid >> 5;
    int lane = tid & 31;
    int gid  = lane >> 2;
    int tig  = lane & 3;
    int wm = (warp >> 2) * 32;
    int wn = (warp & 3) * 32;
    int m0 = blockIdx.y * 64;

    float acc[2][4][4];
#pragma unroll
    for (int i = 0; i < 2; i++)
#pragma unroll
        for (int j = 0; j < 4; j++)
#pragma unroll
            for (int r = 0; r < 4; r++) acc[i][j][r] = 0.0f;

    auto prefetch = [&](float* as, float* ws, int k0) {
#pragma unroll
        for (int r = 0; r < 2; r++) {
            int lin = tid + r * 256;
            int row = lin >> 3;
            int c   = (lin & 7) * 4;
            uint32_t d = s2u(&as[row * PITCH + c]);
            const float* s = &A[(size_t)(m0 + row) * K + k0 + c];
            asm volatile("cp.async.cg.shared.global [%0], [%1], 16;" :: "r"(d), "l"(s) : "memory");
        }
#pragma unroll
        for (int r = 0; r < 4; r++) {
            int lin = tid + r * 256;
            int row = lin >> 3;
            int c   = (lin & 7) * 4;
            uint32_t d = s2u(&ws[row * PITCH + c]);
            const float* s = &W[(size_t)row * K + k0 + c];
            asm volatile("cp.async.cg.shared.global [%0], [%1], 16;" :: "r"(d), "l"(s) : "memory");
        }
    };

    prefetch(As, Ws, 0);
    asm volatile("cp.async.commit_group;" ::: "memory");
    const int nt = K / TBK;
    for (int it = 0; it < nt; it++) {
        if (it + 1 < nt)
            prefetch(As + ((it + 1) & 1) * OA_STG, Ws + ((it + 1) & 1) * OW_STG,
                     (it + 1) * TBK);
        asm volatile("cp.async.commit_group;" ::: "memory");
        asm volatile("cp.async.wait_group 1;" ::: "memory");
        __syncthreads();
        const uint32_t* a_s = reinterpret_cast<const uint32_t*>(As + (it & 1) * OA_STG);
        const uint32_t* w_s = reinterpret_cast<const uint32_t*>(Ws + (it & 1) * OW_STG);
#pragma unroll
        for (int kk = 0; kk < 4; kk++) {
            uint32_t a[2][4], b[4][2];
#pragma unroll
            for (int mf = 0; mf < 2; mf++) {
                int rb = wm + mf * 16;
                a[mf][0] = a_s[(rb + gid)     * PITCH + kk * 8 + tig];
                a[mf][1] = a_s[(rb + gid + 8) * PITCH + kk * 8 + tig];
                a[mf][2] = a_s[(rb + gid)     * PITCH + kk * 8 + tig + 4];
                a[mf][3] = a_s[(rb + gid + 8) * PITCH + kk * 8 + tig + 4];
            }
#pragma unroll
            for (int nf = 0; nf < 4; nf++) {
                int nb = wn + nf * 8 + gid;
                b[nf][0] = w_s[nb * PITCH + kk * 8 + tig];
                b[nf][1] = w_s[nb * PITCH + kk * 8 + tig + 4];
            }
#pragma unroll
            for (int mf = 0; mf < 2; mf++)
#pragma unroll
                for (int nf = 0; nf < 4; nf++)
                    MMA_TF32(acc[mf][nf], a[mf][0], a[mf][1], a[mf][2], a[mf][3],
                             b[nf][0], b[nf][1]);
        }
        __syncthreads();
    }

#pragma unroll
    for (int mf = 0; mf < 2; mf++) {
        int row0 = m0 + wm + mf * 16 + gid;
#pragma unroll
        for (int nf = 0; nf < 4; nf++) {
            int col = wn + nf * 8 + tig * 2;
            size_t o0 = (size_t)row0 * DM + col;
            size_t o1 = (size_t)(row0 + 8) * DM + col;
            acc[mf][nf][0] += h[o0];
            acc[mf][nf][1] += h[o0 + 1];
            acc[mf][nf][2] += h[o1];
            acc[mf][nf][3] += h[o1 + 1];
            if (!LAST) {
                h[o0]     = acc[mf][nf][0];
                h[o0 + 1] = acc[mf][nf][1];
                h[o1]     = acc[mf][nf][2];
                h[o1 + 1] = acc[mf][nf][3];
            }
        }
    }

#pragma unroll
    for (int mf = 0; mf < 2; mf++) {
#pragma unroll
        for (int half = 0; half < 2; half++) {
            float s = 0.f, q = 0.f;
#pragma unroll
            for (int nf = 0; nf < 4; nf++) {
#pragma unroll
                for (int c = 0; c < 2; c++) {
                    float v = acc[mf][nf][half * 2 + c];
                    s += v; q += v * v;
                }
            }
            s += __shfl_xor_sync(0xffffffffu, s, 1);
            s += __shfl_xor_sync(0xffffffffu, s, 2);
            q += __shfl_xor_sync(0xffffffffu, q, 1);
            q += __shfl_xor_sync(0xffffffffu, q, 2);
            int row = wm + mf * 16 + gid + half * 8;
            if (tig == 0) {
                red[0][row][warp & 3] = s;
                red[1][row][warp & 3] = q;
            }
        }
    }
    __syncthreads();

#pragma unroll
    for (int mf = 0; mf < 2; mf++) {
#pragma unroll
        for (int half = 0; half < 2; half++) {
            int row = wm + mf * 16 + gid + half * 8;
            float s = red[0][row][0] + red[0][row][1] + red[0][row][2] + red[0][row][3];
            float q = red[1][row][0] + red[1][row][1] + red[1][row][2] + red[1][row][3];
            float mu = s * (1.0f / DM);
            float var = q * (1.0f / DM) - mu * mu;
            float rsig = rsqrtf(var + 1e-5f);
            size_t rbase = (size_t)(m0 + row) * DM;
#pragma unroll
            for (int nf = 0; nf < 4; nf++) {
#pragma unroll
                for (int c = 0; c < 2; c++) {
                    int col = wn + nf * 8 + tig * 2 + c;
                    float v = (acc[mf][nf][half * 2 + c] - mu) * rsig * lnw[col] + lnb[col];
                    if (LAST) h[rbase + col] = v;
                    else      xn[rbase + col] = tf32r(v);
                }
            }
        }
    }
}

// ---------------- conv1d + silu ----------------
__global__ void conv_silu_kernel(const float* __restrict__ xz, const float* __restrict__ cw,
                                 const float* __restrict__ cb, float* __restrict__ u2) {
    int idx = blockIdx.x * blockDim.x + threadIdx.x;
    if (idx >= (NROWS / 4) * 64) return;
    int d4 = idx & 63;
    int g  = idx >> 6;
    int l0 = (g & (L_ / 4 - 1)) * 4;
    int b  = g >> 11;
    int row0 = b * L_ + l0;

    const float4* cw4 = reinterpret_cast<const float4*>(cw);
    float4 t0 = cw4[d4 * 4 + 0];
    float4 t1 = cw4[d4 * 4 + 1];
    float4 t2 = cw4[d4 * 4 + 2];
    float4 t3 = cw4[d4 * 4 + 3];
    float wA[4] = {t0.x, t0.y, t0.z, t0.w};
    float wB[4] = {t1.x, t1.y, t1.z, t1.w};
    float wC[4] = {t2.x, t2.y, t2.z, t2.w};
    float wD[4] = {t3.x, t3.y, t3.z, t3.w};
    float4 bias = reinterpret_cast<const float4*>(cb)[d4];

    float4 v[7];
#pragma unroll
    for (int k = 0; k < 7; k++) {
        if (l0 - 3 + k >= 0)
            v[k] = reinterpret_cast<const float4*>(xz)[(size_t)(row0 - 3 + k) * 128 + d4];
        else
            v[k] = make_float4(0.f, 0.f, 0.f, 0.f);
    }
#pragma unroll
    for (int j = 0; j < 4; j++) {
        float4 acc = bias;
#pragma unroll
        for (int k = 0; k < 4; k++) {
            float4 x = v[j + k];
            acc.x += x.x * wA[k];
            acc.y += x.y * wB[k];
            acc.z += x.z * wC[k];
            acc.w += x.w * wD[k];
        }
        float4 o;
        o.x = tf32r(acc.x / (1.0f + __expf(-acc.x)));
        o.y = tf32r(acc.y / (1.0f + __expf(-acc.y)));
        o.z = tf32r(acc.z / (1.0f + __expf(-acc.z)));
        o.w = tf32r(acc.w / (1.0f + __expf(-acc.w)));
        reinterpret_cast<float4*>(u2)[(size_t)(row0 + j) * 64 + d4] = o;
    }
}

// ---------------- softplus ----------------
__device__ __forceinline__ float softplusf(float x) {
    return (x > 20.0f) ? x : log1pf(__expf(x));
}

// ---------------- scan phase 1 (t-loop unrolled x8, float4 state IO) ---------------
__global__ __launch_bounds__(256) void scan_ph1(
    const float* __restrict__ u2, const float* __restrict__ dbc,
    const float* __restrict__ Alog,
    const float* __restrict__ dtw, const float* __restrict__ dtb,
    float* __restrict__ dec, float* __restrict__ snd) {
    int c = blockIdx.x, b = blockIdx.y, d = threadIdx.x;
    __shared__ float Bsh[TC * DS];
    __shared__ float Dsh[TC * DTR];
    int rb = b * L_ + c * TC;
    for (int idx = d; idx < TC * 24; idx += 256) {
        int t = idx / 24, f = idx % 24;
        float v = dbc[(size_t)(rb + t) * 40 + f];
        if (f < 8) Dsh[t * 8 + f] = v;
        else       Bsh[t * 16 + f - 8] = v;
    }
    float wreg[DTR];
#pragma unroll
    for (int k = 0; k < DTR; k++) wreg[k] = dtw[d * DTR + k];
    float breg = dtb[d];
    float Ar[DS];
    bool fast = true;
#pragma unroll
    for (int s = 0; s < DS; s++) {
        Ar[s] = -__expf(Alog[d * DS + s]);
        fast = fast && (fabsf(Ar[s] + (float)(s + 1)) < 1e-4f * (float)(s + 1));
    }
    __syncthreads();
    float h[DS], cum[DS];
#pragma unroll
    for (int s = 0; s < DS; s++) { h[s] = 0.0f; cum[s] = 1.0f; }
    float sdt = 0.0f;
    for (int t0 = 0; t0 < TC; t0 += 8) {
        float uv[8];
#pragma unroll
        for (int j = 0; j < 8; j++)
            uv[j] = u2[(size_t)(rb + t0 + j) * DI + d];
#pragma unroll
        for (int j = 0; j < 8; j++) {
            int t = t0 + j;
            float draw = breg;
#pragma unroll
            for (int k = 0; k < DTR; k++) draw += Dsh[t * 8 + k] * wreg[k];
            float dtv = softplusf(draw);
            float xv = dtv * uv[j];
            if (fast) {
                float r = __expf(-dtv);
                float p = 1.0f;
                sdt += dtv;
#pragma unroll
                for (int s = 0; s < DS; s++) {
                    p *= r;
                    h[s] = h[s] * p + xv * Bsh[t * DS + s];
                }
            } else {
#pragma unroll
                for (int s = 0; s < DS; s++) {
                    float dA = __expf(dtv * Ar[s]);
                    h[s] = h[s] * dA + xv * Bsh[t * DS + s];
                    cum[s] *= dA;
                }
            }
        }
    }
    if (fast) {
        float R = __expf(-sdt);
        float p = 1.0f;
#pragma unroll
        for (int s = 0; s < DS; s++) { p *= R; cum[s] = p; }
    }
    size_t base = ((size_t)((b * NCH + c) * DI) + d) * DS;
#pragma unroll
    for (int s = 0; s < DS; s += 4) {
        *reinterpret_cast<float4*>(&snd[base + s]) =
            make_float4(h[s], h[s + 1], h[s + 2], h[s + 3]);
        *reinterpret_cast<float4*>(&dec[base + s]) =
            make_float4(cum[s], cum[s + 1], cum[s + 2], cum[s + 3]);
    }
}

// ---------------- scan phase 2 (unrolled x8) ----------------
__global__ void scan_ph2(const float* __restrict__ dec, const float* __restrict__ snd,
                         float* __restrict__ hin) {
    int b = blockIdx.x;
    int t = blockIdx.y * blockDim.x + threadIdx.x;
    float h = 0.0f;
    size_t stride = DI * DS;
    size_t idx = (size_t)b * NCH * stride + t;
    for (int c = 0; c < NCH; c += 8) {
        float dv[8], sv[8];
#pragma unroll
        for (int j = 0; j < 8; j++) {
            dv[j] = dec[idx + j * stride];
            sv[j] = snd[idx + j * stride];
        }
#pragma unroll
        for (int j = 0; j < 8; j++) {
            hin[idx + j * stride] = h;
            h = h * dv[j] + sv[j];
        }
        idx += 8 * stride;
    }
}

// ---------------- scan phase 3 (t-loop unrolled x8, float4 state IO) ---------------
__global__ __launch_bounds__(256) void scan_ph3(
    const float* __restrict__ u2, const float* __restrict__ dbc,
    const float* __restrict__ xz, const float* __restrict__ Alog,
    const float* __restrict__ dtw, const float* __restrict__ dtb,
    const float* __restrict__ Dp, const float* __restrict__ hin,
    float* __restrict__ yo) {
    int c = blockIdx.x, b = blockIdx.y, d = threadIdx.x;
    __shared__ float Bsh[TC * DS];
    __shared__ float Csh[TC * DS];
    __shared__ float Dsh[TC * DTR];
    int rb = b * L_ + c * TC;
    for (int idx = d; idx < TC * 40; idx += 256) {
        int t = idx / 40, f = idx % 40;
        float v = dbc[(size_t)(rb + t) * 40 + f];
        if (f < 8)       Dsh[t * 8 + f] = v;
        else if (f < 24) Bsh[t * 16 + f - 8] = v;
        else             Csh[t * 16 + f - 24] = v;
    }
    float wreg[DTR];
#pragma unroll
    for (int k = 0; k < DTR; k++) wreg[k] = dtw[d * DTR + k];
    float breg = dtb[d];
    float Ar[DS];
    bool fast = true;
#pragma unroll
    for (int s = 0; s < DS; s++) {
        Ar[s] = -__expf(Alog[d * DS + s]);
        fast = fast && (fabsf(Ar[s] + (float)(s + 1)) < 1e-4f * (float)(s + 1));
    }
    size_t base = ((size_t)((b * NCH + c) * DI) + d) * DS;
    float h[DS];
#pragma unroll
    for (int s = 0; s < DS; s += 4) {
        float4 hv = *reinterpret_cast<const float4*>(&hin[base + s]);
        h[s] = hv.x; h[s + 1] = hv.y; h[s + 2] = hv.z; h[s + 3] = hv.w;
    }
    __syncthreads();
    float dpv = Dp[d];
    for (int t0 = 0; t0 < TC; t0 += 8) {
        float uv[8], zv[8];
#pragma unroll
        for (int j = 0; j < 8; j++) {
            uv[j] = u2[(size_t)(rb + t0 + j) * DI + d];
            zv[j] = xz[(size_t)(rb + t0 + j) * 512 + 256 + d];
        }
#pragma unroll
        for (int j = 0; j < 8; j++) {
            int t = t0 + j;
            float draw = breg;
#pragma unroll
            for (int k = 0; k < DTR; k++) draw += Dsh[t * 8 + k] * wreg[k];
            float dtv = softplusf(draw);
            float xv = dtv * uv[j];
            float y = 0.0f;
            if (fast) {
                float r = __expf(-dtv);
                float p = 1.0f;
#pragma unroll
                for (int s = 0; s < DS; s++) {
                    p *= r;
                    h[s] = h[s] * p + xv * Bsh[t * DS + s];
                    y += h[s] * Csh[t * DS + s];
                }
            } else {
#pragma unroll
                for (int s = 0; s < DS; s++) {
                    float dA = __expf(dtv * Ar[s]);
                    h[s] = h[s] * dA + xv * Bsh[t * DS + s];
                    y += h[s] * Csh[t * DS + s];
                }
            }
            float sig = 1.0f / (1.0f + __expf(-zv[j]));
            yo[(size_t)(rb + t) * DI + d] = tf32r((y + uv[j] * dpv) * (zv[j] * sig));
        }
    }
}

// ---------------- final mean ----------------
__global__ void zero_hg_kernel(float* __restrict__ hg) {
    int i = blockIdx.x * blockDim.x + threadIdx.x;
    if (i < B_ * DM) hg[i] = 0.0f;
}
__global__ void mean_kernel(const float* __restrict__ h, float* __restrict__ hg) {
    int b = blockIdx.x, chunk = blockIdx.y, d = threadIdx.x;
    float acc = 0.0f;
    int base = b * L_ + chunk * 256;
    for (int t = 0; t < 256; t++)
        acc += h[(size_t)(base + t) * DM + d];
    atomicAdd(&hg[b * DM + d], acc * (1.0f / L_));
}

// ---------------- host driver ----------------
extern "C" void kernel_launch(void* const* d_in, const int* in_sizes, int n_in,
                              void* d_out, int out_size) {
    const float* x       = (const float*)d_in[0];
    const float* proj_w  = (const float*)d_in[1];
    const float* proj_b  = (const float*)d_in[2];
    const float* ln_w    = (const float*)d_in[3];
    const float* ln_b    = (const float*)d_in[4];
    const float* in_w    = (const float*)d_in[5];
    const float* conv_w  = (const float*)d_in[6];
    const float* conv_b  = (const float*)d_in[7];
    const float* xproj_w = (const float*)d_in[8];
    const float* dt_w    = (const float*)d_in[9];
    const float* dt_b    = (const float*)d_in[10];
    const float* A_log   = (const float*)d_in[11];
    const float* Dp      = (const float*)d_in[12];
    const float* out_w   = (const float*)d_in[13];
    const float* lnout_w = (const float*)d_in[14];
    const float* lnout_b = (const float*)d_in[15];

    float* h  = (float*)d_out;
    float* hg = h + (size_t)NROWS * DM;

    float *xn, *xz, *u2, *dbc, *yb, *dec, *snd, *hin, *wp;
    cudaGetSymbolAddress((void**)&xn,  g_xn);
    cudaGetSymbolAddress((void**)&xz,  g_xz);
    cudaGetSymbolAddress((void**)&u2,  g_u2);
    cudaGetSymbolAddress((void**)&dbc, g_dbc);
    cudaGetSymbolAddress((void**)&yb,  g_y);
    cudaGetSymbolAddress((void**)&dec, g_dec);
    cudaGetSymbolAddress((void**)&snd, g_snd);
    cudaGetSymbolAddress((void**)&hin, g_hin);
    cudaGetSymbolAddress((void**)&wp,  g_wp);

    cudaFuncSetAttribute(gemm_in, cudaFuncAttributeMaxDynamicSharedMemorySize, IGSMB);
    cudaFuncSetAttribute(gemm_xp, cudaFuncAttributeMaxDynamicSharedMemorySize, XGSMB);
    cudaFuncSetAttribute(gemm_out_fused<false>, cudaFuncAttributeMaxDynamicSharedMemorySize, OGSMB);
    cudaFuncSetAttribute(gemm_out_fused<true>,  cudaFuncAttributeMaxDynamicSharedMemorySize, OGSMB);

    prep_w<<<(WPT + 255) / 256, 256>>>(in_w, xproj_w, out_w, wp);
    init_h_kernel<<<(NROWS * DM + 255) / 256, 256>>>(x, proj_w, proj_b, h);
    ln_kernel<<<NROWS / 8, 256>>>(h, ln_w, ln_b, xn, NROWS);

    for (int i = 0; i < 4; i++) {
        gemm_in<<<dim3(4, NROWS / 128), 256, IGSMB>>>(
            xn, wp + WPI + (size_t)i * 512 * DM, xz);
        conv_silu_kernel<<<((NROWS / 4) * 64 + 255) / 256, 256>>>(
            xz, conv_w + i * DI * 4, conv_b + i * DI, u2);
        gemm_xp<<<dim3(1, NROWS / 128), 256, XGSMB>>>(
            u2, wp + WPX + (size_t)i * 40 * DI, dbc, 40, DI);
        scan_ph1<<<dim3(NCH, B_), 256>>>(u2, dbc, A_log + i * DI * DS,
                                         dt_w + i * DI * DTR, dt_b + i * DI, dec, snd);
        scan_ph2<<<dim3(B_, (DI * DS) / 256), 256>>>(dec, snd, hin);
        scan_ph3<<<dim3(NCH, B_), 256>>>(u2, dbc, xz, A_log + i * DI * DS,
                                         dt_w + i * DI * DTR, dt_b + i * DI,
                                         Dp + i * DI, hin, yb);
        if (i < 3)
            gemm_out_fused<false><<<dim3(1, NROWS / 64), 256, OGSMB>>>(
                yb, wp + WPO + (size_t)i * DM * DI, h, xn,
                ln_w + (i + 1) * DM, ln_b + (i + 1) * DM);
        else
            gemm_out_fused<true><<<dim3(1, NROWS / 64), 256, OGSMB>>>(
                yb, wp + WPO + (size_t)i * DM * DI, h, xn,
                lnout_w, lnout_b);
    }

    zero_hg_kernel<<<(B_ * DM + 255) / 256, 256>>>(hg);
    mean_kernel<<<dim3(B_, L_ / 256), 128>>>(h, hg);
}

// round 16
// speedup vs baseline: 1.0048x; 1.0048x over previous
#include <cuda_runtime.h>
#include <math.h>
#include <stdint.h>

#define B_    8
#define L_    8192
#define DM    128
#define DI    256
#define DS    16
#define DTR   8
#define NROWS (B_*L_)
#define TC    64
#define NCH   (L_/TC)

// ---------------- scratch ----------------
__device__ float g_xn [(size_t)NROWS*DM];
__device__ float g_xz [(size_t)NROWS*512];
__device__ float g_u2 [(size_t)NROWS*DI];
__device__ float g_dbc[(size_t)NROWS*40];
__device__ float g_y  [(size_t)NROWS*DI];
__device__ float g_dec[B_*NCH*DI*DS];
__device__ float g_snd[B_*NCH*DI*DS];
__device__ float g_hin[B_*NCH*DI*DS];
#define WPI 0
#define WPX 262144
#define WPO 303104
#define WPT 434176
__device__ float g_wp[WPT];

// ---------------- helpers ----------------
__device__ __forceinline__ float tf32r(float x) {
    uint32_t r;
    asm("cvt.rna.tf32.f32 %0, %1;" : "=r"(r) : "f"(x));
    return __uint_as_float(r);
}
__device__ __forceinline__ uint32_t s2u(const void* p) {
    uint32_t r;
    asm("{ .reg .u64 t; cvta.to.shared.u64 t, %1; cvt.u32.u64 %0, t; }" : "=r"(r) : "l"(p));
    return r;
}
#define MMA_TF32(acc, A0, A1, A2, A3, B0, B1)                                  \
    asm volatile(                                                              \
        "mma.sync.aligned.m16n8k8.row.col.f32.tf32.tf32.f32 "                  \
        "{%0,%1,%2,%3}, {%4,%5,%6,%7}, {%8,%9}, {%0,%1,%2,%3};"                \
        : "+f"((acc)[0]), "+f"((acc)[1]), "+f"((acc)[2]), "+f"((acc)[3])       \
        : "r"(A0), "r"(A1), "r"(A2), "r"(A3), "r"(B0), "r"(B1))

// ---------------- weight prep ----------------
__global__ void prep_w(const float* __restrict__ in_w, const float* __restrict__ xproj_w,
                       const float* __restrict__ out_w, float* __restrict__ wp) {
    int i = blockIdx.x * blockDim.x + threadIdx.x;
    if (i < WPX)            wp[i] = tf32r(in_w[i]);
    else if (i < WPO)       wp[i] = tf32r(xproj_w[i - WPX]);
    else if (i < WPT)       wp[i] = tf32r(out_w[i - WPO]);
}

// ---------------- init ----------------
__global__ void init_h_kernel(const float* __restrict__ x, const float* __restrict__ pw,
                              const float* __restrict__ pb, float* __restrict__ h) {
    int idx = blockIdx.x * blockDim.x + threadIdx.x;
    if (idx >= NROWS * DM) return;
    int d = idx & (DM - 1);
    int row = idx >> 7;
    int b = row >> 13;
    int l = row & (L_ - 1);
    float acc = pb[d];
#pragma unroll
    for (int c = 0; c < 3; c++)
        acc += x[(b * 3 + c) * L_ + l] * pw[d * 3 + c];
    h[idx] = acc;
}

// ---------------- layernorm (layer-0 only) ----------------
__global__ void ln_kernel(const float* __restrict__ in, const float* __restrict__ w,
                          const float* __restrict__ bias, float* __restrict__ out,
                          int nrows) {
    int gwarp = (blockIdx.x * blockDim.x + threadIdx.x) >> 5;
    int lane  = threadIdx.x & 31;
    if (gwarp >= nrows) return;
    const float4 v = *reinterpret_cast<const float4*>(&in[(size_t)gwarp * DM + lane * 4]);
    float s = v.x + v.y + v.z + v.w;
#pragma unroll
    for (int o = 16; o; o >>= 1) s += __shfl_xor_sync(0xffffffffu, s, o);
    float mu = s * (1.0f / DM);
    float d0 = v.x - mu, d1 = v.y - mu, d2 = v.z - mu, d3 = v.w - mu;
    float q = d0 * d0 + d1 * d1 + d2 * d2 + d3 * d3;
#pragma unroll
    for (int o = 16; o; o >>= 1) q += __shfl_xor_sync(0xffffffffu, q, o);
    float r = rsqrtf(q * (1.0f / DM) + 1e-5f);
    const float4 wv = *reinterpret_cast<const float4*>(&w[lane * 4]);
    const float4 bv = *reinterpret_cast<const float4*>(&bias[lane * 4]);
    float4 o4;
    o4.x = tf32r(d0 * r * wv.x + bv.x);
    o4.y = tf32r(d1 * r * wv.y + bv.y);
    o4.z = tf32r(d2 * r * wv.z + bv.z);
    o4.w = tf32r(d3 * r * wv.w + bv.w);
    *reinterpret_cast<float4*>(&out[(size_t)gwarp * DM + lane * 4]) = o4;
}

// ---------------- common GEMM constants ----------------
#define TBK 32
#define PITCH 36

// ---------------- in_proj GEMM: 128x128 tile, TBK=32 ----------------
#define ISTG (128*PITCH)
#define IGSMB (2*2*ISTG*4)

__global__ __launch_bounds__(256) void gemm_in(
    const float* __restrict__ A, const float* __restrict__ W,
    float* __restrict__ C) {
    extern __shared__ float sm[];
    float* As = sm;
    float* Ws = sm + 2 * ISTG;
    const int K = DM;
    int tid  = threadIdx.x;
    int warp = tid >> 5;
    int lane = tid & 31;
    int gid  = lane >> 2;
    int tig  = lane & 3;
    int wm = (warp >> 2) * 64;
    int wn = (warp & 3) * 32;
    int m0 = blockIdx.y * 128;
    int n0 = blockIdx.x * 128;

    float acc[4][4][4];
#pragma unroll
    for (int i = 0; i < 4; i++)
#pragma unroll
        for (int j = 0; j < 4; j++)
#pragma unroll
            for (int r = 0; r < 4; r++) acc[i][j][r] = 0.0f;

    auto prefetch = [&](float* as, float* ws, int k0) {
#pragma unroll
        for (int r = 0; r < 4; r++) {
            int lin = tid + r * 256;
            int row = lin >> 3;
            int c   = (lin & 7) * 4;
            uint32_t d = s2u(&as[row * PITCH + c]);
            const float* s = &A[(size_t)(m0 + row) * K + k0 + c];
            asm volatile("cp.async.cg.shared.global [%0], [%1], 16;" :: "r"(d), "l"(s) : "memory");
        }
#pragma unroll
        for (int r = 0; r < 4; r++) {
            int lin = tid + r * 256;
            int row = lin >> 3;
            int c   = (lin & 7) * 4;
            uint32_t d = s2u(&ws[row * PITCH + c]);
            const float* s = &W[(size_t)(n0 + row) * K + k0 + c];
            asm volatile("cp.async.cg.shared.global [%0], [%1], 16;" :: "r"(d), "l"(s) : "memory");
        }
    };

    prefetch(As, Ws, 0);
    asm volatile("cp.async.commit_group;" ::: "memory");
    const int nt = K / TBK;
    for (int it = 0; it < nt; it++) {
        if (it + 1 < nt)
            prefetch(As + ((it + 1) & 1) * ISTG, Ws + ((it + 1) & 1) * ISTG,
                     (it + 1) * TBK);
        asm volatile("cp.async.commit_group;" ::: "memory");
        asm volatile("cp.async.wait_group 1;" ::: "memory");
        __syncthreads();
        const uint32_t* a_s = reinterpret_cast<const uint32_t*>(As + (it & 1) * ISTG);
        const uint32_t* w_s = reinterpret_cast<const uint32_t*>(Ws + (it & 1) * ISTG);
#pragma unroll
        for (int kk = 0; kk < 4; kk++) {
            uint32_t a[4][4], b[4][2];
#pragma unroll
            for (int mf = 0; mf < 4; mf++) {
                int rb = wm + mf * 16;
                a[mf][0] = a_s[(rb + gid)     * PITCH + kk * 8 + tig];
                a[mf][1] = a_s[(rb + gid + 8) * PITCH + kk * 8 + tig];
                a[mf][2] = a_s[(rb + gid)     * PITCH + kk * 8 + tig + 4];
                a[mf][3] = a_s[(rb + gid + 8) * PITCH + kk * 8 + tig + 4];
            }
#pragma unroll
            for (int nf = 0; nf < 4; nf++) {
                int nb = wn + nf * 8 + gid;
                b[nf][0] = w_s[nb * PITCH + kk * 8 + tig];
                b[nf][1] = w_s[nb * PITCH + kk * 8 + tig + 4];
            }
#pragma unroll
            for (int mf = 0; mf < 4; mf++)
#pragma unroll
                for (int nf = 0; nf < 4; nf++)
                    MMA_TF32(acc[mf][nf], a[mf][0], a[mf][1], a[mf][2], a[mf][3],
                             b[nf][0], b[nf][1]);
        }
        __syncthreads();
    }

#pragma unroll
    for (int mf = 0; mf < 4; mf++) {
        int row0 = m0 + wm + mf * 16 + gid;
#pragma unroll
        for (int nf = 0; nf < 4; nf++) {
            int col = n0 + wn + nf * 8 + tig * 2;
            size_t o0 = (size_t)row0 * 512 + col;
            size_t o1 = (size_t)(row0 + 8) * 512 + col;
            C[o0]     = acc[mf][nf][0];
            C[o0 + 1] = acc[mf][nf][1];
            C[o1]     = acc[mf][nf][2];
            C[o1 + 1] = acc[mf][nf][3];
        }
    }
}

// ---------------- x_proj GEMM: 128x64 tile (N=40) ----------------
#define XA_STG (128*PITCH)
#define XW_STG (64*PITCH)
#define XGSMB (2*(XA_STG+XW_STG)*4)

__global__ __launch_bounds__(256) void gemm_xp(
    const float* __restrict__ A, const float* __restrict__ W,
    float* __restrict__ C, int N, int K) {
    extern __shared__ float sm[];
    float* As = sm;
    float* Ws = sm + 2 * XA_STG;
    int tid  = threadIdx.x;
    int warp = tid >> 5;
    int lane = tid & 31;
    int gid  = lane >> 2;
    int tig  = lane & 3;
    int wm = (warp >> 1) * 32;
    int wn = (warp & 1) * 32;
    int m0 = blockIdx.y * 128;
    int nt = K / TBK;

    float acc[2][4][4];
#pragma unroll
    for (int i = 0; i < 2; i++)
#pragma unroll
        for (int j = 0; j < 4; j++)
#pragma unroll
            for (int r = 0; r < 4; r++) acc[i][j][r] = 0.0f;

    auto prefetch = [&](float* as, float* ws, int k0) {
#pragma unroll
        for (int r = 0; r < 4; r++) {
            int lin = tid + r * 256;
            int row = lin >> 3;
            int c   = (lin & 7) * 4;
            uint32_t d = s2u(&as[row * PITCH + c]);
            const float* s = &A[(size_t)(m0 + row) * K + k0 + c];
            asm volatile("cp.async.cg.shared.global [%0], [%1], 16;" :: "r"(d), "l"(s) : "memory");
        }
#pragma unroll
        for (int r = 0; r < 2; r++) {
            int lin = tid + r * 256;
            int row = lin >> 3;
            int c   = (lin & 7) * 4;
            if (row < N) {
                uint32_t d = s2u(&ws[row * PITCH + c]);
                const float* s = &W[(size_t)row * K + k0 + c];
                asm volatile("cp.async.cg.shared.global [%0], [%1], 16;" :: "r"(d), "l"(s) : "memory");
            }
        }
    };

    prefetch(As, Ws, 0);
    asm volatile("cp.async.commit_group;" ::: "memory");
    for (int it = 0; it < nt; it++) {
        if (it + 1 < nt)
            prefetch(As + ((it + 1) & 1) * XA_STG, Ws + ((it + 1) & 1) * XW_STG,
                     (it + 1) * TBK);
        asm volatile("cp.async.commit_group;" ::: "memory");
        asm volatile("cp.async.wait_group 1;" ::: "memory");
        __syncthreads();
        const uint32_t* a_s = reinterpret_cast<const uint32_t*>(As + (it & 1) * XA_STG);
        const uint32_t* w_s = reinterpret_cast<const uint32_t*>(Ws + (it & 1) * XW_STG);
#pragma unroll
        for (int kk = 0; kk < 4; kk++) {
            uint32_t a[2][4], b[4][2];
#pragma unroll
            for (int mf = 0; mf < 2; mf++) {
                int rb = wm + mf * 16;
                a[mf][0] = a_s[(rb + gid)     * PITCH + kk * 8 + tig];
                a[mf][1] = a_s[(rb + gid + 8) * PITCH + kk * 8 + tig];
                a[mf][2] = a_s[(rb + gid)     * PITCH + kk * 8 + tig + 4];
                a[mf][3] = a_s[(rb + gid + 8) * PITCH + kk * 8 + tig + 4];
            }
#pragma unroll
            for (int nf = 0; nf < 4; nf++) {
                int nb = wn + nf * 8 + gid;
                b[nf][0] = w_s[nb * PITCH + kk * 8 + tig];
                b[nf][1] = w_s[nb * PITCH + kk * 8 + tig + 4];
            }
#pragma unroll
            for (int mf = 0; mf < 2; mf++)
#pragma unroll
                for (int nf = 0; nf < 4; nf++)
                    MMA_TF32(acc[mf][nf], a[mf][0], a[mf][1], a[mf][2], a[mf][3],
                             b[nf][0], b[nf][1]);
        }
        __syncthreads();
    }

#pragma unroll
    for (int mf = 0; mf < 2; mf++) {
        int row0 = m0 + wm + mf * 16 + gid;
#pragma unroll
        for (int nf = 0; nf < 4; nf++) {
            int col = wn + nf * 8 + tig * 2;
            if (col < N) {
                size_t o0 = (size_t)row0 * N + col;
                size_t o1 = (size_t)(row0 + 8) * N + col;
                C[o0] = acc[mf][nf][0];
                if (col + 1 < N) C[o0 + 1] = acc[mf][nf][1];
                C[o1] = acc[mf][nf][2];
                if (col + 1 < N) C[o1 + 1] = acc[mf][nf][3];
            }
        }
    }
}

// ---------------- out-proj GEMM: 64x128 tile + residual + fused LayerNorm ----------
#define OA_STG (64*PITCH)
#define OW_STG (128*PITCH)
#define OGSMB (2*(OA_STG+OW_STG)*4)

template <bool LAST>
__global__ __launch_bounds__(256) void gemm_out_fused(
    const float* __restrict__ A, const float* __restrict__ W,
    float* __restrict__ h, float* __restrict__ xn,
    const float* __restrict__ lnw, const float* __restrict__ lnb) {
    extern __shared__ float sm[];
    float* As = sm;
    float* Ws = sm + 2 * OA_STG;
    __shared__ float red[2][64][4];
    const int K = DI;
    int tid  = threadIdx.x;
    int warp = tid >> 5;
    int lane = tid & 31;
    int gid  = lane >> 2;
    int tig  = lane & 3;
    int wm = (warp >> 2) * 32;
    int wn = (warp & 3) * 32;
    int m0 = blockIdx.y * 64;

    float acc[2][4][4];
#pragma unroll
    for (int i = 0; i < 2; i++)
#pragma unroll
        for (int j = 0; j < 4; j++)
#pragma unroll
            for (int r = 0; r < 4; r++) acc[i][j][r] = 0.0f;

    auto prefetch = [&](float* as, float* ws, int k0) {
#pragma unroll
        for (int r = 0; r < 2; r++) {
            int lin = tid + r * 256;
            int row = lin >> 3;
            int c   = (lin & 7) * 4;
            uint32_t d = s2u(&as[row * PITCH + c]);
            const float* s = &A[(size_t)(m0 + row) * K + k0 + c];
            asm volatile("cp.async.cg.shared.global [%0], [%1], 16;" :: "r"(d), "l"(s) : "memory");
        }
#pragma unroll
        for (int r = 0; r < 4; r++) {
            int lin = tid + r * 256;
            int row = lin >> 3;
            int c   = (lin & 7) * 4;
            uint32_t d = s2u(&ws[row * PITCH + c]);
            const float* s = &W[(size_t)row * K + k0 + c];
            asm volatile("cp.async.cg.shared.global [%0], [%1], 16;" :: "r"(d), "l"(s) : "memory");
        }
    };

    prefetch(As, Ws, 0);
    asm volatile("cp.async.commit_group;" ::: "memory");
    const int nt = K / TBK;
    for (int it = 0; it < nt; it++) {
        if (it + 1 < nt)
            prefetch(As + ((it + 1) & 1) * OA_STG, Ws + ((it + 1) & 1) * OW_STG,
                     (it + 1) * TBK);
        asm volatile("cp.async.commit_group;" ::: "memory");
        asm volatile("cp.async.wait_group 1;" ::: "memory");
        __syncthreads();
        const uint32_t* a_s = reinterpret_cast<const uint32_t*>(As + (it & 1) * OA_STG);
        const uint32_t* w_s = reinterpret_cast<const uint32_t*>(Ws + (it & 1) * OW_STG);
#pragma unroll
        for (int kk = 0; kk < 4; kk++) {
            uint32_t a[2][4], b[4][2];
#pragma unroll
            for (int mf = 0; mf < 2; mf++) {
                int rb = wm + mf * 16;
                a[mf][0] = a_s[(rb + gid)     * PITCH + kk * 8 + tig];
                a[mf][1] = a_s[(rb + gid + 8) * PITCH + kk * 8 + tig];
                a[mf][2] = a_s[(rb + gid)     * PITCH + kk * 8 + tig + 4];
                a[mf][3] = a_s[(rb + gid + 8) * PITCH + kk * 8 + tig + 4];
            }
#pragma unroll
            for (int nf = 0; nf < 4; nf++) {
                int nb = wn + nf * 8 + gid;
                b[nf][0] = w_s[nb * PITCH + kk * 8 + tig];
                b[nf][1] = w_s[nb * PITCH + kk * 8 + tig + 4];
            }
#pragma unroll
            for (int mf = 0; mf < 2; mf++)
#pragma unroll
                for (int nf = 0; nf < 4; nf++)
                    MMA_TF32(acc[mf][nf], a[mf][0], a[mf][1], a[mf][2], a[mf][3],
                             b[nf][0], b[nf][1]);
        }
        __syncthreads();
    }

#pragma unroll
    for (int mf = 0; mf < 2; mf++) {
        int row0 = m0 + wm + mf * 16 + gid;
#pragma unroll
        for (int nf = 0; nf < 4; nf++) {
            int col = wn + nf * 8 + tig * 2;
            size_t o0 = (size_t)row0 * DM + col;
            size_t o1 = (size_t)(row0 + 8) * DM + col;
            acc[mf][nf][0] += h[o0];
            acc[mf][nf][1] += h[o0 + 1];
            acc[mf][nf][2] += h[o1];
            acc[mf][nf][3] += h[o1 + 1];
            if (!LAST) {
                h[o0]     = acc[mf][nf][0];
                h[o0 + 1] = acc[mf][nf][1];
                h[o1]     = acc[mf][nf][2];
                h[o1 + 1] = acc[mf][nf][3];
            }
        }
    }

#pragma unroll
    for (int mf = 0; mf < 2; mf++) {
#pragma unroll
        for (int half = 0; half < 2; half++) {
            float s = 0.f, q = 0.f;
#pragma unroll
            for (int nf = 0; nf < 4; nf++) {
#pragma unroll
                for (int c = 0; c < 2; c++) {
                    float v = acc[mf][nf][half * 2 + c];
                    s += v; q += v * v;
                }
            }
            s += __shfl_xor_sync(0xffffffffu, s, 1);
            s += __shfl_xor_sync(0xffffffffu, s, 2);
            q += __shfl_xor_sync(0xffffffffu, q, 1);
            q += __shfl_xor_sync(0xffffffffu, q, 2);
            int row = wm + mf * 16 + gid + half * 8;
            if (tig == 0) {
                red[0][row][warp & 3] = s;
                red[1][row][warp & 3] = q;
            }
        }
    }
    __syncthreads();

#pragma unroll
    for (int mf = 0; mf < 2; mf++) {
#pragma unroll
        for (int half = 0; half < 2; half++) {
            int row = wm + mf * 16 + gid + half * 8;
            float s = red[0][row][0] + red[0][row][1] + red[0][row][2] + red[0][row][3];
            float q = red[1][row][0] + red[1][row][1] + red[1][row][2] + red[1][row][3];
            float mu = s * (1.0f / DM);
            float var = q * (1.0f / DM) - mu * mu;
            float rsig = rsqrtf(var + 1e-5f);
            size_t rbase = (size_t)(m0 + row) * DM;
#pragma unroll
            for (int nf = 0; nf < 4; nf++) {
#pragma unroll
                for (int c = 0; c < 2; c++) {
                    int col = wn + nf * 8 + tig * 2 + c;
                    float v = (acc[mf][nf][half * 2 + c] - mu) * rsig * lnw[col] + lnb[col];
                    if (LAST) h[rbase + col] = v;
                    else      xn[rbase + col] = tf32r(v);
                }
            }
        }
    }
}

// ---------------- conv1d + silu ----------------
__global__ void conv_silu_kernel(const float* __restrict__ xz, const float* __restrict__ cw,
                                 const float* __restrict__ cb, float* __restrict__ u2) {
    int idx = blockIdx.x * blockDim.x + threadIdx.x;
    if (idx >= (NROWS / 4) * 64) return;
    int d4 = idx & 63;
    int g  = idx >> 6;
    int l0 = (g & (L_ / 4 - 1)) * 4;
    int b  = g >> 11;
    int row0 = b * L_ + l0;

    const float4* cw4 = reinterpret_cast<const float4*>(cw);
    float4 t0 = cw4[d4 * 4 + 0];
    float4 t1 = cw4[d4 * 4 + 1];
    float4 t2 = cw4[d4 * 4 + 2];
    float4 t3 = cw4[d4 * 4 + 3];
    float wA[4] = {t0.x, t0.y, t0.z, t0.w};
    float wB[4] = {t1.x, t1.y, t1.z, t1.w};
    float wC[4] = {t2.x, t2.y, t2.z, t2.w};
    float wD[4] = {t3.x, t3.y, t3.z, t3.w};
    float4 bias = reinterpret_cast<const float4*>(cb)[d4];

    float4 v[7];
#pragma unroll
    for (int k = 0; k < 7; k++) {
        if (l0 - 3 + k >= 0)
            v[k] = reinterpret_cast<const float4*>(xz)[(size_t)(row0 - 3 + k) * 128 + d4];
        else
            v[k] = make_float4(0.f, 0.f, 0.f, 0.f);
    }
#pragma unroll
    for (int j = 0; j < 4; j++) {
        float4 acc = bias;
#pragma unroll
        for (int k = 0; k < 4; k++) {
            float4 x = v[j + k];
            acc.x += x.x * wA[k];
            acc.y += x.y * wB[k];
            acc.z += x.z * wC[k];
            acc.w += x.w * wD[k];
        }
        float4 o;
        o.x = tf32r(acc.x / (1.0f + __expf(-acc.x)));
        o.y = tf32r(acc.y / (1.0f + __expf(-acc.y)));
        o.z = tf32r(acc.z / (1.0f + __expf(-acc.z)));
        o.w = tf32r(acc.w / (1.0f + __expf(-acc.w)));
        reinterpret_cast<float4*>(u2)[(size_t)(row0 + j) * 64 + d4] = o;
    }
}

// ---------------- softplus ----------------
__device__ __forceinline__ float softplusf(float x) {
    return (x > 20.0f) ? x : log1pf(__expf(x));
}

// ---------------- scan phase 1 (t-loop unrolled x8, float4 state IO) ---------------
__global__ __launch_bounds__(256) void scan_ph1(
    const float* __restrict__ u2, const float* __restrict__ dbc,
    const float* __restrict__ Alog,
    const float* __restrict__ dtw, const float* __restrict__ dtb,
    float* __restrict__ dec, float* __restrict__ snd) {
    int c = blockIdx.x, b = blockIdx.y, d = threadIdx.x;
    __shared__ float Bsh[TC * DS];
    __shared__ float Dsh[TC * DTR];
    int rb = b * L_ + c * TC;
    for (int idx = d; idx < TC * 24; idx += 256) {
        int t = idx / 24, f = idx % 24;
        float v = dbc[(size_t)(rb + t) * 40 + f];
        if (f < 8) Dsh[t * 8 + f] = v;
        else       Bsh[t * 16 + f - 8] = v;
    }
    float wreg[DTR];
#pragma unroll
    for (int k = 0; k < DTR; k++) wreg[k] = dtw[d * DTR + k];
    float breg = dtb[d];
    float Ar[DS];
    bool fast = true;
#pragma unroll
    for (int s = 0; s < DS; s++) {
        Ar[s] = -__expf(Alog[d * DS + s]);
        fast = fast && (fabsf(Ar[s] + (float)(s + 1)) < 1e-4f * (float)(s + 1));
    }
    __syncthreads();
    float h[DS], cum[DS];
#pragma unroll
    for (int s = 0; s < DS; s++) { h[s] = 0.0f; cum[s] = 1.0f; }
    float sdt = 0.0f;
    for (int t0 = 0; t0 < TC; t0 += 8) {
        float uv[8];
#pragma unroll
        for (int j = 0; j < 8; j++)
            uv[j] = u2[(size_t)(rb + t0 + j) * DI + d];
#pragma unroll
        for (int j = 0; j < 8; j++) {
            int t = t0 + j;
            float draw = breg;
#pragma unroll
            for (int k = 0; k < DTR; k++) draw += Dsh[t * 8 + k] * wreg[k];
            float dtv = softplusf(draw);
            float xv = dtv * uv[j];
            if (fast) {
                float r = __expf(-dtv);
                float p = 1.0f;
                sdt += dtv;
#pragma unroll
                for (int s = 0; s < DS; s++) {
                    p *= r;
                    h[s] = h[s] * p + xv * Bsh[t * DS + s];
                }
            } else {
#pragma unroll
                for (int s = 0; s < DS; s++) {
                    float dA = __expf(dtv * Ar[s]);
                    h[s] = h[s] * dA + xv * Bsh[t * DS + s];
                    cum[s] *= dA;
                }
            }
        }
    }
    if (fast) {
        float R = __expf(-sdt);
        float p = 1.0f;
#pragma unroll
        for (int s = 0; s < DS; s++) { p *= R; cum[s] = p; }
    }
    size_t base = ((size_t)((b * NCH + c) * DI) + d) * DS;
#pragma unroll
    for (int s = 0; s < DS; s += 4) {
        *reinterpret_cast<float4*>(&snd[base + s]) =
            make_float4(h[s], h[s + 1], h[s + 2], h[s + 3]);
        *reinterpret_cast<float4*>(&dec[base + s]) =
            make_float4(cum[s], cum[s + 1], cum[s + 2], cum[s + 3]);
    }
}

// ---------------- scan phase 2 (unrolled x8) ----------------
__global__ void scan_ph2(const float* __restrict__ dec, const float* __restrict__ snd,
                         float* __restrict__ hin) {
    int b = blockIdx.x;
    int t = blockIdx.y * blockDim.x + threadIdx.x;
    float h = 0.0f;
    size_t stride = DI * DS;
    size_t idx = (size_t)b * NCH * stride + t;
    for (int c = 0; c < NCH; c += 8) {
        float dv[8], sv[8];
#pragma unroll
        for (int j = 0; j < 8; j++) {
            dv[j] = dec[idx + j * stride];
            sv[j] = snd[idx + j * stride];
        }
#pragma unroll
        for (int j = 0; j < 8; j++) {
            hin[idx + j * stride] = h;
            h = h * dv[j] + sv[j];
        }
        idx += 8 * stride;
    }
}

// ---------------- scan phase 3 (t-loop unrolled x8, float4 state IO) ---------------
__global__ __launch_bounds__(256) void scan_ph3(
    const float* __restrict__ u2, const float* __restrict__ dbc,
    const float* __restrict__ xz, const float* __restrict__ Alog,
    const float* __restrict__ dtw, const float* __restrict__ dtb,
    const float* __restrict__ Dp, const float* __restrict__ hin,
    float* __restrict__ yo) {
    int c = blockIdx.x, b = blockIdx.y, d = threadIdx.x;
    __shared__ float Bsh[TC * DS];
    __shared__ float Csh[TC * DS];
    __shared__ float Dsh[TC * DTR];
    int rb = b * L_ + c * TC;
    for (int idx = d; idx < TC * 40; idx += 256) {
        int t = idx / 40, f = idx % 40;
        float v = dbc[(size_t)(rb + t) * 40 + f];
        if (f < 8)       Dsh[t * 8 + f] = v;
        else if (f < 24) Bsh[t * 16 + f - 8] = v;
        else             Csh[t * 16 + f - 24] = v;
    }
    float wreg[DTR];
#pragma unroll
    for (int k = 0; k < DTR; k++) wreg[k] = dtw[d * DTR + k];
    float breg = dtb[d];
    float Ar[DS];
    bool fast = true;
#pragma unroll
    for (int s = 0; s < DS; s++) {
        Ar[s] = -__expf(Alog[d * DS + s]);
        fast = fast && (fabsf(Ar[s] + (float)(s + 1)) < 1e-4f * (float)(s + 1));
    }
    size_t base = ((size_t)((b * NCH + c) * DI) + d) * DS;
    float h[DS];
#pragma unroll
    for (int s = 0; s < DS; s += 4) {
        float4 hv = *reinterpret_cast<const float4*>(&hin[base + s]);
        h[s] = hv.x; h[s + 1] = hv.y; h[s + 2] = hv.z; h[s + 3] = hv.w;
    }
    __syncthreads();
    float dpv = Dp[d];
    for (int t0 = 0; t0 < TC; t0 += 8) {
        float uv[8], zv[8];
#pragma unroll
        for (int j = 0; j < 8; j++) {
            uv[j] = u2[(size_t)(rb + t0 + j) * DI + d];
            zv[j] = xz[(size_t)(rb + t0 + j) * 512 + 256 + d];
        }
#pragma unroll
        for (int j = 0; j < 8; j++) {
            int t = t0 + j;
            float draw = breg;
#pragma unroll
            for (int k = 0; k < DTR; k++) draw += Dsh[t * 8 + k] * wreg[k];
            float dtv = softplusf(draw);
            float xv = dtv * uv[j];
            float y = 0.0f;
            if (fast) {
                float r = __expf(-dtv);
                float p = 1.0f;
#pragma unroll
                for (int s = 0; s < DS; s++) {
                    p *= r;
                    h[s] = h[s] * p + xv * Bsh[t * DS + s];
                    y += h[s] * Csh[t * DS + s];
                }
            } else {
#pragma unroll
                for (int s = 0; s < DS; s++) {
                    float dA = __expf(dtv * Ar[s]);
                    h[s] = h[s] * dA + xv * Bsh[t * DS + s];
                    y += h[s] * Csh[t * DS + s];
                }
            }
            float sig = 1.0f / (1.0f + __expf(-zv[j]));
            yo[(size_t)(rb + t) * DI + d] = tf32r((y + uv[j] * dpv) * (zv[j] * sig));
        }
    }
}

// ---------------- final mean ----------------
__global__ void zero_hg_kernel(float* __restrict__ hg) {
    int i = blockIdx.x * blockDim.x + threadIdx.x;
    if (i < B_ * DM) hg[i] = 0.0f;
}
__global__ void mean_kernel(const float* __restrict__ h, float* __restrict__ hg) {
    int b = blockIdx.x, chunk = blockIdx.y, d = threadIdx.x;
    float acc = 0.0f;
    int base = b * L_ + chunk * 256;
    for (int t = 0; t < 256; t++)
        acc += h[(size_t)(base + t) * DM + d];
    atomicAdd(&hg[b * DM + d], acc * (1.0f / L_));
}

// ---------------- host driver ----------------
extern "C" void kernel_launch(void* const* d_in, const int* in_sizes, int n_in,
                              void* d_out, int out_size) {
    const float* x       = (const float*)d_in[0];
    const float* proj_w  = (const float*)d_in[1];
    const float* proj_b  = (const float*)d_in[2];
    const float* ln_w    = (const float*)d_in[3];
    const float* ln_b    = (const float*)d_in[4];
    const float* in_w    = (const float*)d_in[5];
    const float* conv_w  = (const float*)d_in[6];
    const float* conv_b  = (const float*)d_in[7];
    const float* xproj_w = (const float*)d_in[8];
    const float* dt_w    = (const float*)d_in[9];
    const float* dt_b    = (const float*)d_in[10];
    const float* A_log   = (const float*)d_in[11];
    const float* Dp      = (const float*)d_in[12];
    const float* out_w   = (const float*)d_in[13];
    const float* lnout_w = (const float*)d_in[14];
    const float* lnout_b = (const float*)d_in[15];

    float* h  = (float*)d_out;
    float* hg = h + (size_t)NROWS * DM;

    float *xn, *xz, *u2, *dbc, *yb, *dec, *snd, *hin, *wp;
    cudaGetSymbolAddress((void**)&xn,  g_xn);
    cudaGetSymbolAddress((void**)&xz,  g_xz);
    cudaGetSymbolAddress((void**)&u2,  g_u2);
    cudaGetSymbolAddress((void**)&dbc, g_dbc);
    cudaGetSymbolAddress((void**)&yb,  g_y);
    cudaGetSymbolAddress((void**)&dec, g_dec);
    cudaGetSymbolAddress((void**)&snd, g_snd);
    cudaGetSymbolAddress((void**)&hin, g_hin);
    cudaGetSymbolAddress((void**)&wp,  g_wp);

    cudaFuncSetAttribute(gemm_in, cudaFuncAttributeMaxDynamicSharedMemorySize, IGSMB);
    cudaFuncSetAttribute(gemm_xp, cudaFuncAttributeMaxDynamicSharedMemorySize, XGSMB);
    cudaFuncSetAttribute(gemm_out_fused<false>, cudaFuncAttributeMaxDynamicSharedMemorySize, OGSMB);
    cudaFuncSetAttribute(gemm_out_fused<true>,  cudaFuncAttributeMaxDynamicSharedMemorySize, OGSMB);

    prep_w<<<(WPT + 255) / 256, 256>>>(in_w, xproj_w, out_w, wp);
    init_h_kernel<<<(NROWS * DM + 255) / 256, 256>>>(x, proj_w, proj_b, h);
    ln_kernel<<<NROWS / 8, 256>>>(h, ln_w, ln_b, xn, NROWS);

    for (int i = 0; i < 4; i++) {
        gemm_in<<<dim3(4, NROWS / 128), 256, IGSMB>>>(
            xn, wp + WPI + (size_t)i * 512 * DM, xz);
        conv_silu_kernel<<<((NROWS / 4) * 64 + 255) / 256, 256>>>(
            xz, conv_w + i * DI * 4, conv_b + i * DI, u2);
        gemm_xp<<<dim3(1, NROWS / 128), 256, XGSMB>>>(
            u2, wp + WPX + (size_t)i * 40 * DI, dbc, 40, DI);
        scan_ph1<<<dim3(NCH, B_), 256>>>(u2, dbc, A_log + i * DI * DS,
                                         dt_w + i * DI * DTR, dt_b + i * DI, dec, snd);
        scan_ph2<<<dim3(B_, (DI * DS) / 256), 256>>>(dec, snd, hin);
        scan_ph3<<<dim3(NCH, B_), 256>>>(u2, dbc, xz, A_log + i * DI * DS,
                                         dt_w + i * DI * DTR, dt_b + i * DI,
                                         Dp + i * DI, hin, yb);
        if (i < 3)
            gemm_out_fused<false><<<dim3(1, NROWS / 64), 256, OGSMB>>>(
                yb, wp + WPO + (size_t)i * DM * DI, h, xn,
                ln_w + (i + 1) * DM, ln_b + (i + 1) * DM);
        else
            gemm_out_fused<true><<<dim3(1, NROWS / 64), 256, OGSMB>>>(
                yb, wp + WPO + (size_t)i * DM * DI, h, xn,
                lnout_w, lnout_b);
    }

    zero_hg_kernel<<<(B_ * DM + 255) / 256, 256>>>(hg);
    mean_kernel<<<dim3(B_, L_ / 256), 128>>>(h, hg);
}